// round 9
// baseline (speedup 1.0000x reference)
#include <cuda_runtime.h>
#include <math.h>

// Problem constants
#define B 128
#define L 512
#define H 512
#define V 50000

#define NBLK 128
#define NTHR 256

#define KST  132    // staged A row stride [k][b] (conflict-free STS/LDS.128)
#define ABUF 1056   // 8k * KST
#define WSCR 2112   // per-warp scratch floats (2 stage bufs / 16x128 Ptile)

typedef unsigned long long ull;

// ---------------------------------------------------------------------------
__device__ float    g_h[2][B * H];
__device__ float    g_c[B * H];
__device__ int      g_tokT[L * B];
__device__ unsigned g_arrive;

__device__ __forceinline__ void fma2(ull& d, ull a, ull b) {
    asm("fma.rn.f32x2 %0, %1, %2, %0;" : "+l"(d) : "l"(a), "l"(b));
}
__device__ __forceinline__ float sigf(float x) {
    return 1.f / (1.f + __expf(-x));
}

// ---------------------------------------------------------------------------
__global__ void k_init(const int* __restrict__ tokens) {
    int i = blockIdx.x * blockDim.x + threadIdx.x;
    if (i < B * H) { g_h[0][i] = 0.f; g_h[1][i] = 0.f; g_c[i] = 0.f; }
    if (i < L * B) {
        int t = i >> 7, b = i & 127;
        g_tokT[i] = tokens[b * L + t];
    }
    if (i == 0) g_arrive = 0u;
}

// ---------------------------------------------------------------------------
// Persistent LSTM recurrence, warp-level split-K.
// Block bx owns h-cols [4bx,4bx+4) -> 16 gate rows. Warp w owns k-range
// [128w, 128w+128) (w<4: embedding half, w>=4: h half). Per thread: 16 rows
// x 4 batches of fma2 accumulators; a via 1 LDS.128/k, w via 8 broadcast
// LDS.128/k from a pre-duplicated (w,w) table. Warp-private staging in 8-k
// double-buffered chunks -> no intra-step block barriers. Per step: one
// __syncthreads + 8-way partial reduction + pointwise + grid barrier.
// ---------------------------------------------------------------------------
extern __shared__ float smem[];

__global__ void __launch_bounds__(NTHR, 1)
k_lstm(const int*   __restrict__ lengths, const float* __restrict__ emb,
       const float* __restrict__ Wih,     const float* __restrict__ Whh,
       const float* __restrict__ bih,     const float* __restrict__ bhh,
       int t0, int t1)
{
    float* Wd  = smem;               // [1024][16 dup pairs] = 32768 floats
    float* Sc  = Wd + 32768;         // 8 warps x WSCR
    float* bsm = Sc + 8 * WSCR;      // [16]
    int*   tks = (int*)(bsm + 16);   // [128] tokens of current step

    const int tid  = threadIdx.x;
    const int bx   = blockIdx.x;
    const int w    = tid >> 5;
    const int lane = tid & 31;

    // ---- pre-duplicated weight table ----
    for (int idx = tid; idx < 16 * 1024; idx += NTHR) {
        int r = idx >> 10;              // local gate row 0..15
        int k = idx & 1023;
        int g = r >> 2, cc = r & 3;
        int grow = g * 512 + bx * 4 + cc;
        float wv = (k < 512) ? Wih[grow * 512 + k]
                             : Whh[grow * 512 + (k - 512)];
        Wd[k * 32 + 2 * r]     = wv;
        Wd[k * 32 + 2 * r + 1] = wv;
    }
    if (tid < 16) {
        int g = tid >> 2, cc = tid & 3;
        int grow = g * 512 + bx * 4 + cc;
        bsm[tid] = bih[grow] + bhh[grow];
    }
    if (tid < 128) tks[tid] = g_tokT[t0 * 128 + tid];

    // ---- pointwise state: 2 states per thread ----
    const int pcol = tid & 3;
    const int pb   = tid >> 2;          // 0..63 ; second state pb+64
    const int hcol = bx * 4 + pcol;
    const int len0 = lengths[pb];
    const int len1 = lengths[pb + 64];
    float c0 = g_c[pb * H + hcol],        c1 = g_c[(pb + 64) * H + hcol];
    float h0 = g_h[t0 & 1][pb * H + hcol], h1 = g_h[t0 & 1][(pb + 64) * H + hcol];

    // ---- staging roles ----
    const int kq = lane & 7;            // k within 8-k chunk
    const int bq = lane >> 3;           // 0..3
    const int kbaseW = w * 128;         // warp's global k base
    const bool isEmb = (w < 4);
    float* myScr = Sc + w * WSCR;

    __syncthreads();

    for (int t = t0; t < t1; t++) {
        const int rb = t & 1, wb = rb ^ 1;
        const float* __restrict__ hprev = g_h[rb];

        ull acc0[16], acc1[16];
        #pragma unroll
        for (int r = 0; r < 16; r++) { acc0[r] = 0ull; acc1[r] = 0ull; }

        float v[32];

        // ---- stage chunk 0 ----
        {
            int kg = kbaseW + kq;
            if (isEmb) {
                #pragma unroll
                for (int m = 0; m < 32; m++)
                    v[m] = __ldg(emb + (long)tks[4 * m + bq] * 512 + kg);
            } else {
                const float* hp = hprev + (kg - 512);
                #pragma unroll
                for (int m = 0; m < 32; m++)
                    v[m] = __ldcg(hp + (4 * m + bq) * 512);
            }
            float* dst = myScr + kq * KST + bq;
            #pragma unroll
            for (int m = 0; m < 32; m++) dst[4 * m] = v[m];
        }
        __syncwarp();

        for (int c = 0; c < 16; c++) {
            // prefetch chunk c+1
            if (c < 15) {
                int kg = kbaseW + (c + 1) * 8 + kq;
                if (isEmb) {
                    #pragma unroll
                    for (int m = 0; m < 32; m++)
                        v[m] = __ldg(emb + (long)tks[4 * m + bq] * 512 + kg);
                } else {
                    const float* hp = hprev + (kg - 512);
                    #pragma unroll
                    for (int m = 0; m < 32; m++)
                        v[m] = __ldcg(hp + (4 * m + bq) * 512);
                }
            }

            // compute chunk c (8 k)
            {
                const float* Ab = myScr + (c & 1) * ABUF + 4 * lane;
                const float* Wk = Wd + (kbaseW + c * 8) * 32;
                #pragma unroll
                for (int k = 0; k < 8; k++) {
                    ulonglong2 a = *(const ulonglong2*)(Ab + k * KST);
                    const float* Wkk = Wk + k * 32;
                    #pragma unroll
                    for (int j = 0; j < 8; j++) {
                        ulonglong2 wp = *(const ulonglong2*)(Wkk + 4 * j);
                        fma2(acc0[2 * j],     a.x, wp.x);
                        fma2(acc1[2 * j],     a.y, wp.x);
                        fma2(acc0[2 * j + 1], a.x, wp.y);
                        fma2(acc1[2 * j + 1], a.y, wp.y);
                    }
                }
            }

            // commit prefetched chunk
            if (c < 15) {
                float* dst = myScr + ((c + 1) & 1) * ABUF + kq * KST + bq;
                #pragma unroll
                for (int m = 0; m < 32; m++) dst[4 * m] = v[m];
            }
            __syncwarp();
        }

        // ---- write partial tile (overlays dead staging buffers) ----
        #pragma unroll
        for (int r = 0; r < 16; r++) {
            ulonglong2 p; p.x = acc0[r]; p.y = acc1[r];
            *(ulonglong2*)(myScr + r * 128 + 4 * lane) = p;
        }
        __syncthreads();

        // ---- reduce 8 partials + pointwise (2 states/thread) ----
        {
            float xi0 = bsm[pcol],      xf0 = bsm[4 + pcol];
            float xg0 = bsm[8 + pcol],  xo0 = bsm[12 + pcol];
            float xi1 = xi0, xf1 = xf0, xg1 = xg0, xo1 = xo0;
            #pragma unroll
            for (int ww = 0; ww < 8; ww++) {
                const float* P = Sc + ww * WSCR;
                xi0 += P[(pcol)      * 128 + pb];
                xf0 += P[(4 + pcol)  * 128 + pb];
                xg0 += P[(8 + pcol)  * 128 + pb];
                xo0 += P[(12 + pcol) * 128 + pb];
                xi1 += P[(pcol)      * 128 + pb + 64];
                xf1 += P[(4 + pcol)  * 128 + pb + 64];
                xg1 += P[(8 + pcol)  * 128 + pb + 64];
                xo1 += P[(12 + pcol) * 128 + pb + 64];
            }
            if (t < len0) {
                float ig = sigf(xi0), fg = sigf(xf0), og = sigf(xo0);
                float gg = 2.f * sigf(2.f * xg0) - 1.f;
                c0 = fg * c0 + ig * gg;
                h0 = og * (2.f * sigf(2.f * c0) - 1.f);
            }
            if (t < len1) {
                float ig = sigf(xi1), fg = sigf(xf1), og = sigf(xo1);
                float gg = 2.f * sigf(2.f * xg1) - 1.f;
                c1 = fg * c1 + ig * gg;
                h1 = og * (2.f * sigf(2.f * c1) - 1.f);
            }
            g_h[wb][pb * H + hcol]        = h0;
            g_h[wb][(pb + 64) * H + hcol] = h1;
        }

        // ---- tokens for next step ----
        if (tid < 128 && t + 1 < L) tks[tid] = g_tokT[(t + 1) * 128 + tid];

        // ---- grid barrier ----
        __threadfence();
        __syncthreads();
        if (tid == 0) {
            unsigned target = (unsigned)NBLK * (unsigned)(t + 1);
            atomicAdd(&g_arrive, 1u);
            while (*(volatile unsigned*)&g_arrive < target) { }
        }
        __syncthreads();
    }

    // ---- segment handoff ----
    g_c[pb * H + hcol]        = c0;
    g_c[(pb + 64) * H + hcol] = c1;
}

// ---------------------------------------------------------------------------
// FC: out[b, v] = h_final[b, :] . W_fc[v, :] + b_fc[v]
// ---------------------------------------------------------------------------
__global__ void __launch_bounds__(256, 1)
k_fc(const float* __restrict__ Wfc, const float* __restrict__ bfc,
     float* __restrict__ out)
{
    __shared__ float As_[16][128];
    __shared__ float Bs_[16][128];

    const int vBase = blockIdx.x * 128;
    const int tid   = threadIdx.x;
    const int ty    = tid >> 4;
    const int tx    = tid & 15;

    const float* __restrict__ hptr = g_h[0];

    float acc[8][8];
    #pragma unroll
    for (int i = 0; i < 8; i++)
        #pragma unroll
        for (int j = 0; j < 8; j++) acc[i][j] = 0.f;

    for (int k0 = 0; k0 < H; k0 += 16) {
        #pragma unroll
        for (int r = 0; r < 8; r++) {
            int idx = tid + 256 * r;
            int m = idx >> 4, k = idx & 15;
            As_[k][m] = hptr[m * H + k0 + k];
        }
        #pragma unroll
        for (int r = 0; r < 8; r++) {
            int idx = tid + 256 * r;
            int vv = idx >> 4, k = idx & 15;
            int gv = vBase + vv;
            Bs_[k][vv] = (gv < V) ? Wfc[gv * H + k0 + k] : 0.f;
        }
        __syncthreads();

        #pragma unroll
        for (int k = 0; k < 16; k++) {
            float a[8], b[8];
            *(float4*)&a[0] = *(const float4*)&As_[k][ty * 8];
            *(float4*)&a[4] = *(const float4*)&As_[k][ty * 8 + 4];
            *(float4*)&b[0] = *(const float4*)&Bs_[k][tx * 8];
            *(float4*)&b[4] = *(const float4*)&Bs_[k][tx * 8 + 4];
            #pragma unroll
            for (int i = 0; i < 8; i++)
                #pragma unroll
                for (int j = 0; j < 8; j++)
                    acc[i][j] = fmaf(a[i], b[j], acc[i][j]);
        }
        __syncthreads();
    }

    #pragma unroll
    for (int i = 0; i < 8; i++) {
        int m = ty * 8 + i;
        #pragma unroll
        for (int j = 0; j < 8; j++) {
            int gv = vBase + tx * 8 + j;
            if (gv < V) out[m * V + gv] = acc[i][j] + bfc[gv];
        }
    }
}

// ---------------------------------------------------------------------------
extern "C" void kernel_launch(void* const* d_in, const int* in_sizes, int n_in,
                              void* d_out, int out_size)
{
    const int*   tokens  = (const int*)  d_in[0];
    const int*   lengths = (const int*)  d_in[1];
    const float* emb     = (const float*)d_in[2];
    const float* Wih     = (const float*)d_in[3];
    const float* Whh     = (const float*)d_in[4];
    const float* bih     = (const float*)d_in[5];
    const float* bhh     = (const float*)d_in[6];
    const float* Wfc     = (const float*)d_in[7];
    const float* bfc     = (const float*)d_in[8];
    float* out = (float*)d_out;

    const int smemBytes = (32768 + 8 * WSCR + 16 + 128) * 4;
    static bool attrSet = false;
    if (!attrSet) {
        cudaFuncSetAttribute(k_lstm, cudaFuncAttributeMaxDynamicSharedMemorySize,
                             smemBytes);
        attrSet = true;
    }

    k_init<<<(B * H + 255) / 256, 256>>>(tokens);
    for (int seg = 0; seg < 4; seg++) {
        k_lstm<<<NBLK, NTHR, smemBytes>>>(lengths, emb, Wih, Whh, bih, bhh,
                                          seg * (L / 4), (seg + 1) * (L / 4));
    }
    k_fc<<<(V + 127) / 128, 256>>>(Wfc, bfc, out);
}

// round 10
// speedup vs baseline: 1.0296x; 1.0296x over previous
#include <cuda_runtime.h>
#include <math.h>

// Problem constants
#define B 128
#define L 512
#define H 512
#define V 50000

#define NBLK 128
#define NTHR 512

#define KST   36     // staged A row stride (16B-aligned, 2-way STS worst case)
#define ABUFW 576    // one staging buffer: 16 k * KST
#define WPRIV 1152   // per-warp scratch: 2 staging buffers

typedef unsigned long long ull;

// ---------------------------------------------------------------------------
__device__ float    g_h[2][B * H];
__device__ float    g_c[B * H];
__device__ int      g_tokT[L * B];
__device__ unsigned g_arrive;

__device__ __forceinline__ void fma2(ull& d, ull a, ull b) {
    asm("fma.rn.f32x2 %0, %1, %2, %0;" : "+l"(d) : "l"(a), "l"(b));
}
__device__ __forceinline__ float sigf(float x) {
    return 1.f / (1.f + __expf(-x));
}

// ---------------------------------------------------------------------------
__global__ void k_init(const int* __restrict__ tokens) {
    int i = blockIdx.x * blockDim.x + threadIdx.x;
    if (i < B * H) { g_h[0][i] = 0.f; g_h[1][i] = 0.f; g_c[i] = 0.f; }
    if (i < L * B) {
        int t = i >> 7, b = i & 127;
        g_tokT[i] = tokens[b * L + t];
    }
    if (i == 0) g_arrive = 0u;
}

// ---------------------------------------------------------------------------
// Persistent LSTM recurrence over t in [t0, t1).
// Block bx owns h-cols [4bx,4bx+4) -> 16 gate rows. 16 warps = 4 K-sets
// (k in [256s,256s+256)) x 4 batch-groups (32 batches). Thread tile:
// 4 rows x 4 batches -> per k: 1 LDS.128(a) + 2 LDS.128(dup w-pairs) +
// 8 fma2. Warp-private double-buffered staging (16-k chunks, coalesced
// LDG). Partial tiles overlay dead staging smem; one reduction +
// pointwise + grid barrier per step. c/h in regs; handoff via g_c/g_h.
// ---------------------------------------------------------------------------
extern __shared__ float smem[];

__global__ void __launch_bounds__(NTHR, 1)
k_lstm(const int*   __restrict__ lengths, const float* __restrict__ emb,
       const float* __restrict__ Wih,     const float* __restrict__ Whh,
       const float* __restrict__ bih,     const float* __restrict__ bhh,
       int t0, int t1)
{
    float* Wd  = smem;               // [1024][32] dup (w,w) pairs = 32768 fl
    float* Sc  = Wd + 32768;         // 16 warps x WPRIV (partials overlay)
    float* bsm = Sc + 16 * WPRIV;    // [16] combined biases
    int*   tks = (int*)(bsm + 16);   // [128] tokens of current step

    const int tid  = threadIdx.x;
    const int bx   = blockIdx.x;
    const int w    = tid >> 5;
    const int lane = tid & 31;

    // ---- pre-duplicated weight table ----
    for (int idx = tid; idx < 16 * 1024; idx += NTHR) {
        int r = idx >> 10;              // local gate row 0..15
        int k = idx & 1023;
        int g = r >> 2, cc = r & 3;
        int grow = g * 512 + bx * 4 + cc;
        float wv = (k < 512) ? Wih[grow * 512 + k]
                             : Whh[grow * 512 + (k - 512)];
        Wd[k * 32 + 2 * r]     = wv;
        Wd[k * 32 + 2 * r + 1] = wv;
    }
    if (tid < 16) {
        int g = tid >> 2, cc = tid & 3;
        int grow = g * 512 + bx * 4 + cc;
        bsm[tid] = bih[grow] + bhh[grow];
    }
    if (tid < 128) tks[tid] = g_tokT[t0 * 128 + tid];

    // ---- warp roles ----
    const int set  = w >> 2;            // K-set: k in [256set, 256set+256)
    const int ws   = w & 3;             // batch group
    const int b0w  = 32 * ws;
    const int kb0  = 256 * set;
    const bool isEmb = (set < 2);
    float* myS = Sc + w * WPRIV;

    // staging lanes: kq = k within 16-chunk, hi = row parity
    const int kq = lane & 15;
    const int hi = lane >> 4;

    // compute lanes: bq batch-quad (4 batches), rq row-quad (4 rows)
    const int bq = lane & 7;
    const int rq = lane >> 3;
    const int r0 = 4 * rq;

    // ---- pointwise state: 1 (batch,col) per thread ----
    const int pcol = tid & 3;
    const int pb   = tid >> 2;          // 0..127
    const int hcol = bx * 4 + pcol;
    const int len  = lengths[pb];
    float c_reg = g_c[pb * H + hcol];
    float h_reg = g_h[t0 & 1][pb * H + hcol];

    __syncthreads();

    for (int t = t0; t < t1; t++) {
        const int rb = t & 1, wb = rb ^ 1;
        const float* __restrict__ hprev = g_h[rb];

        ull acc[8];
        #pragma unroll
        for (int i = 0; i < 8; i++) acc[i] = 0ull;

        float vv[16];

        // ---- stage chunk 0 (k = kb0 .. kb0+15) ----
        {
            int kg = kb0 + kq;
            if (isEmb) {
                #pragma unroll
                for (int jj = 0; jj < 16; jj++)
                    vv[jj] = __ldg(emb + (long)tks[b0w + 2 * jj + hi] * 512 + kg);
            } else {
                const float* hp = hprev + (kg - 512);
                #pragma unroll
                for (int jj = 0; jj < 16; jj++)
                    vv[jj] = __ldcg(hp + (b0w + 2 * jj + hi) * 512);
            }
            float* dst = myS + kq * KST;
            #pragma unroll
            for (int jj = 0; jj < 16; jj++) dst[2 * jj + hi] = vv[jj];
        }
        __syncwarp();

        for (int c = 0; c < 16; c++) {
            // prefetch chunk c+1
            if (c < 15) {
                int kg = kb0 + 16 * (c + 1) + kq;
                if (isEmb) {
                    #pragma unroll
                    for (int jj = 0; jj < 16; jj++)
                        vv[jj] = __ldg(emb + (long)tks[b0w + 2 * jj + hi] * 512 + kg);
                } else {
                    const float* hp = hprev + (kg - 512);
                    #pragma unroll
                    for (int jj = 0; jj < 16; jj++)
                        vv[jj] = __ldcg(hp + (b0w + 2 * jj + hi) * 512);
                }
            }

            // compute chunk c (16 k): 11 instr per k, 16 FMA per thread
            {
                const float* Ab = myS + (c & 1) * ABUFW + 4 * bq;
                const float* Wk = Wd + (kb0 + 16 * c) * 32 + 8 * rq;
                #pragma unroll
                for (int k = 0; k < 16; k++) {
                    ulonglong2 a   = *(const ulonglong2*)(Ab + k * KST);
                    ulonglong2 w01 = *(const ulonglong2*)(Wk + k * 32);
                    ulonglong2 w23 = *(const ulonglong2*)(Wk + k * 32 + 4);
                    fma2(acc[0], a.x, w01.x);  fma2(acc[1], a.y, w01.x);
                    fma2(acc[2], a.x, w01.y);  fma2(acc[3], a.y, w01.y);
                    fma2(acc[4], a.x, w23.x);  fma2(acc[5], a.y, w23.x);
                    fma2(acc[6], a.x, w23.y);  fma2(acc[7], a.y, w23.y);
                }
            }

            // commit prefetched chunk
            if (c < 15) {
                float* dst = myS + ((c + 1) & 1) * ABUFW + kq * KST;
                #pragma unroll
                for (int jj = 0; jj < 16; jj++) dst[2 * jj + hi] = vv[jj];
            }
            __syncwarp();
        }

        // ---- partial tiles overlay staging smem: P_s[16][128] ----
        __syncthreads();                 // all warps done reading staging bufs
        {
            float* P = Sc + set * 2048;
            #pragma unroll
            for (int rr = 0; rr < 4; rr++) {
                ulonglong2 pr;
                pr.x = acc[2 * rr];
                pr.y = acc[2 * rr + 1];
                *(ulonglong2*)(P + (r0 + rr) * 128 + b0w + 4 * bq) = pr;
            }
        }
        __syncthreads();

        // ---- reduce 4 K-set partials + pointwise (1 state/thread) ----
        {
            float xi = bsm[pcol],      xf = bsm[4 + pcol];
            float xg = bsm[8 + pcol],  xo = bsm[12 + pcol];
            #pragma unroll
            for (int s = 0; s < 4; s++) {
                const float* P = Sc + s * 2048;
                xi += P[(pcol)      * 128 + pb];
                xf += P[(4 + pcol)  * 128 + pb];
                xg += P[(8 + pcol)  * 128 + pb];
                xo += P[(12 + pcol) * 128 + pb];
            }
            if (t < len) {
                float ig = sigf(xi), fg = sigf(xf), og = sigf(xo);
                float gg = 2.f * sigf(2.f * xg) - 1.f;
                c_reg = fg * c_reg + ig * gg;
                h_reg = og * (2.f * sigf(2.f * c_reg) - 1.f);
            }
            g_h[wb][pb * H + hcol] = h_reg;
        }

        // ---- tokens for next step ----
        if (tid < 128 && t + 1 < L) tks[tid] = g_tokT[(t + 1) * 128 + tid];

        // ---- grid barrier ----
        __threadfence();
        __syncthreads();
        if (tid == 0) {
            unsigned target = (unsigned)NBLK * (unsigned)(t + 1);
            atomicAdd(&g_arrive, 1u);
            while (*(volatile unsigned*)&g_arrive < target) { }
        }
        __syncthreads();
    }

    // ---- segment handoff ----
    g_c[pb * H + hcol] = c_reg;
}

// ---------------------------------------------------------------------------
// FC: out[b, v] = h_final[b, :] . W_fc[v, :] + b_fc[v]
// ---------------------------------------------------------------------------
__global__ void __launch_bounds__(256, 1)
k_fc(const float* __restrict__ Wfc, const float* __restrict__ bfc,
     float* __restrict__ out)
{
    __shared__ float As_[16][128];
    __shared__ float Bs_[16][128];

    const int vBase = blockIdx.x * 128;
    const int tid   = threadIdx.x;
    const int ty    = tid >> 4;
    const int tx    = tid & 15;

    const float* __restrict__ hptr = g_h[0];

    float acc[8][8];
    #pragma unroll
    for (int i = 0; i < 8; i++)
        #pragma unroll
        for (int j = 0; j < 8; j++) acc[i][j] = 0.f;

    for (int k0 = 0; k0 < H; k0 += 16) {
        #pragma unroll
        for (int r = 0; r < 8; r++) {
            int idx = tid + 256 * r;
            int m = idx >> 4, k = idx & 15;
            As_[k][m] = hptr[m * H + k0 + k];
        }
        #pragma unroll
        for (int r = 0; r < 8; r++) {
            int idx = tid + 256 * r;
            int vv = idx >> 4, k = idx & 15;
            int gv = vBase + vv;
            Bs_[k][vv] = (gv < V) ? Wfc[gv * H + k0 + k] : 0.f;
        }
        __syncthreads();

        #pragma unroll
        for (int k = 0; k < 16; k++) {
            float a[8], b[8];
            *(float4*)&a[0] = *(const float4*)&As_[k][ty * 8];
            *(float4*)&a[4] = *(const float4*)&As_[k][ty * 8 + 4];
            *(float4*)&b[0] = *(const float4*)&Bs_[k][tx * 8];
            *(float4*)&b[4] = *(const float4*)&Bs_[k][tx * 8 + 4];
            #pragma unroll
            for (int i = 0; i < 8; i++)
                #pragma unroll
                for (int j = 0; j < 8; j++)
                    acc[i][j] = fmaf(a[i], b[j], acc[i][j]);
        }
        __syncthreads();
    }

    #pragma unroll
    for (int i = 0; i < 8; i++) {
        int m = ty * 8 + i;
        #pragma unroll
        for (int j = 0; j < 8; j++) {
            int gv = vBase + tx * 8 + j;
            if (gv < V) out[m * V + gv] = acc[i][j] + bfc[gv];
        }
    }
}

// ---------------------------------------------------------------------------
extern "C" void kernel_launch(void* const* d_in, const int* in_sizes, int n_in,
                              void* d_out, int out_size)
{
    const int*   tokens  = (const int*)  d_in[0];
    const int*   lengths = (const int*)  d_in[1];
    const float* emb     = (const float*)d_in[2];
    const float* Wih     = (const float*)d_in[3];
    const float* Whh     = (const float*)d_in[4];
    const float* bih     = (const float*)d_in[5];
    const float* bhh     = (const float*)d_in[6];
    const float* Wfc     = (const float*)d_in[7];
    const float* bfc     = (const float*)d_in[8];
    float* out = (float*)d_out;

    const int smemBytes = (32768 + 16 * WPRIV + 16 + 128) * 4;
    static bool attrSet = false;
    if (!attrSet) {
        cudaFuncSetAttribute(k_lstm, cudaFuncAttributeMaxDynamicSharedMemorySize,
                             smemBytes);
        attrSet = true;
    }

    k_init<<<(B * H + 255) / 256, 256>>>(tokens);
    for (int seg = 0; seg < 4; seg++) {
        k_lstm<<<NBLK, NTHR, smemBytes>>>(lengths, emb, Wih, Whh, bih, bhh,
                                          seg * (L / 4), (seg + 1) * (L / 4));
    }
    k_fc<<<(V + 127) / 128, 256>>>(Wfc, bfc, out);
}

// round 11
// speedup vs baseline: 1.4374x; 1.3960x over previous
#include <cuda_runtime.h>
#include <math.h>

// Problem constants
#define B 128
#define L 512
#define H 512
#define V 50000

#define NBLK 128
#define NTHR 512

typedef unsigned long long ull;

// ---------------------------------------------------------------------------
// Device globals (static scratch; no runtime allocation)
// ---------------------------------------------------------------------------
__device__ float    g_hT[2][H * B];       // transposed hidden state [k][b], x2
__device__ float    g_c[B * H];           // cell state (segment handoff)
__device__ int      g_tokT[L * B];        // transposed tokens [t][b]
__device__ unsigned g_arrive;             // grid barrier counter
__device__ float    g_xp[(long)L * 2048 * B];  // x_proj + biases: [t][grow][b]

// ---------------------------------------------------------------------------
__device__ __forceinline__ ull packf2(float x, float y) {
    ull r; asm("mov.b64 %0, {%1, %2};" : "=l"(r) : "f"(x), "f"(y)); return r;
}
__device__ __forceinline__ float2 unpackf2(ull v) {
    float2 r; asm("mov.b64 {%0, %1}, %2;" : "=f"(r.x), "=f"(r.y) : "l"(v));
    return r;
}
__device__ __forceinline__ void fma2(ull& d, ull a, ull b) {
    asm("fma.rn.f32x2 %0, %1, %2, %0;" : "+l"(d) : "l"(a), "l"(b));
}
__device__ __forceinline__ float sigf(float x) {
    return 1.f / (1.f + __expf(-x));
}

// ---------------------------------------------------------------------------
__global__ void k_init(const int* __restrict__ tokens) {
    int i = blockIdx.x * blockDim.x + threadIdx.x;
    if (i < H * B) { g_hT[0][i] = 0.f; g_hT[1][i] = 0.f; g_c[i] = 0.f; }
    if (i < L * B) {
        int t = i >> 7, b = i & 127;
        g_tokT[i] = tokens[b * L + t];
    }
    if (i == 0) g_arrive = 0u;
}

// ---------------------------------------------------------------------------
// x_proj GEMM: g_xp[t][grow][b] = sum_k Wih[grow][k]*emb[tok[t][b]][k]
//                               + bih[grow] + bhh[grow]
// Tile: 128 grows x 128 b, K=512 in 16-k tiles. 256 thr, 8x8/thread, fma2.
// ---------------------------------------------------------------------------
__global__ void __launch_bounds__(256, 2)
k_xproj(const float* __restrict__ Wih, const float* __restrict__ bih,
        const float* __restrict__ bhh, const float* __restrict__ emb)
{
    __shared__ float As[16 * 132];
    __shared__ float Bs[16 * 132];
    __shared__ float bsum[128];
    __shared__ int   tok[128];

    const int gt  = blockIdx.x;     // grow tile 0..15
    const int t   = blockIdx.y;     // timestep 0..511
    const int tid = threadIdx.x;
    const int ty  = tid >> 4;       // 0..15 -> rows ty*8..
    const int tx  = tid & 15;       // 0..15 -> b cols tx*8..

    if (tid < 128) {
        tok[tid]  = g_tokT[t * 128 + tid];
        int grow  = gt * 128 + tid;
        bsum[tid] = bih[grow] + bhh[grow];
    }
    __syncthreads();

    ull acc[8][4];
    #pragma unroll
    for (int i = 0; i < 8; i++)
        #pragma unroll
        for (int j = 0; j < 4; j++) acc[i][j] = 0ull;

    for (int k0 = 0; k0 < 512; k0 += 16) {
        // stage A: 128 grows x 16 k
        #pragma unroll
        for (int i = 0; i < 2; i++) {
            int idx = tid + 256 * i;
            int r = idx >> 2, f = idx & 3;
            float4 w4 = *(const float4*)(Wih + (gt * 128 + r) * 512 + k0 + 4 * f);
            As[(4 * f + 0) * 132 + r] = w4.x;
            As[(4 * f + 1) * 132 + r] = w4.y;
            As[(4 * f + 2) * 132 + r] = w4.z;
            As[(4 * f + 3) * 132 + r] = w4.w;
        }
        // stage B: 128 b x 16 k (embedding gather)
        #pragma unroll
        for (int i = 0; i < 2; i++) {
            int idx = tid + 256 * i;
            int b = idx >> 2, f = idx & 3;
            float4 v4 = *(const float4*)(emb + (long)tok[b] * 512 + k0 + 4 * f);
            Bs[(4 * f + 0) * 132 + b] = v4.x;
            Bs[(4 * f + 1) * 132 + b] = v4.y;
            Bs[(4 * f + 2) * 132 + b] = v4.z;
            Bs[(4 * f + 3) * 132 + b] = v4.w;
        }
        __syncthreads();

        #pragma unroll
        for (int k = 0; k < 16; k++) {
            float a8[8];
            *(float4*)&a8[0] = *(const float4*)(As + k * 132 + ty * 8);
            *(float4*)&a8[4] = *(const float4*)(As + k * 132 + ty * 8 + 4);
            ulonglong2 b01 = *(const ulonglong2*)(Bs + k * 132 + tx * 8);
            ulonglong2 b23 = *(const ulonglong2*)(Bs + k * 132 + tx * 8 + 4);
            #pragma unroll
            for (int i = 0; i < 8; i++) {
                ull ad = packf2(a8[i], a8[i]);
                fma2(acc[i][0], ad, b01.x);
                fma2(acc[i][1], ad, b01.y);
                fma2(acc[i][2], ad, b23.x);
                fma2(acc[i][3], ad, b23.y);
            }
        }
        __syncthreads();
    }

    float* outp = g_xp + (long)t * 262144 + (gt * 128) * 128;
    #pragma unroll
    for (int i = 0; i < 8; i++) {
        int r = ty * 8 + i;
        float bias = bsum[r];
        float2 p0 = unpackf2(acc[i][0]), p1 = unpackf2(acc[i][1]);
        float2 p2 = unpackf2(acc[i][2]), p3 = unpackf2(acc[i][3]);
        float4 o0 = make_float4(p0.x + bias, p0.y + bias, p1.x + bias, p1.y + bias);
        float4 o1 = make_float4(p2.x + bias, p2.y + bias, p3.x + bias, p3.y + bias);
        *(float4*)(outp + r * 128 + tx * 8)     = o0;
        *(float4*)(outp + r * 128 + tx * 8 + 4) = o1;
    }
}

// ---------------------------------------------------------------------------
// Persistent LSTM recurrence over t in [t0, t1). K = 512 (h half only).
// Block bx owns h-cols [4bx,4bx+4) -> 16 gate rows; dup-weight table in smem.
// 16 warps = 4 K-sets (128 k) x 4 batch-groups (32 b). Per k: LDS.128(a) +
// 2x LDS.128(dup w) + 8 fma2. Staging from transposed g_hT via LDG.128 ->
// STS.128, set-local named barriers. x_proj read from g_xp in pointwise.
// ---------------------------------------------------------------------------
extern __shared__ float smem[];

__global__ void __launch_bounds__(NTHR, 1)
k_lstm(const int* __restrict__ lengths, const float* __restrict__ Whh,
       int t0, int t1)
{
    float* Wd = smem;                 // [512][32] dup (w,w) pairs = 16384 fl
    float* As = Wd + 16384;           // [4 sets][2 buf][16 k][132]
    float* Gs = As + 4 * 2 * 16 * 132; // [4 sets][16][132] partials

    const int tid  = threadIdx.x;
    const int bx   = blockIdx.x;
    const int w    = tid >> 5;
    const int lane = tid & 31;

    // ---- dup-weight table (W_hh only, K=512) ----
    for (int idx = tid; idx < 16 * 512; idx += NTHR) {
        int k  = idx >> 4;
        int lr = idx & 15;
        int g = lr >> 2, cc = lr & 3;
        int grow = g * 512 + bx * 4 + cc;
        float wv = Whh[grow * 512 + k];
        Wd[k * 32 + 2 * lr]     = wv;
        Wd[k * 32 + 2 * lr + 1] = wv;
    }

    // ---- warp roles ----
    const int set = w & 3;            // K-set: k in [128set, 128set+128)
    const int w4  = w >> 2;           // 0..3: batch group [32w4, 32w4+32)
    const int kb0 = 128 * set;
    float* AsS = As + set * (2 * 16 * 132);

    const int r4 = lane & 3;          // rows 4r4..4r4+3
    const int bq = lane >> 2;         // 0..7: 4-batch quad within group

    // ---- pointwise roles ----
    const int pb = tid >> 2;          // batch 0..127
    const int pc = tid & 3;
    const int hcol = bx * 4 + pc;
    const int len  = lengths[pb];
    float c_reg = g_c[pb * H + hcol];
    float h_reg = g_hT[t0 & 1][hcol * 128 + pb];

    __syncthreads();

    for (int t = t0; t < t1; t++) {
        const int rb = t & 1, wb = rb ^ 1;
        const float* __restrict__ hT = g_hT[rb];

        // prefetch x_proj for my (pb, pc)
        float xq[4];
        #pragma unroll
        for (int g = 0; g < 4; g++)
            xq[g] = __ldg(g_xp + (long)t * 262144
                          + (g * 512 + bx * 4 + pc) * 128 + pb);

        ull acc[8];
        #pragma unroll
        for (int i = 0; i < 8; i++) acc[i] = 0ull;

        float4 v4[4];

        // ---- stage chunk 0 (k rows kb0+4w4+m, all 128 b) ----
        #pragma unroll
        for (int m = 0; m < 4; m++) {
            int kg = kb0 + 4 * w4 + m;
            v4[m] = *(const float4*)(hT + kg * 128 + 4 * lane);  // via L2
        }
        #pragma unroll
        for (int m = 0; m < 4; m++)
            *(float4*)(AsS + (4 * w4 + m) * 132 + 4 * lane) = v4[m];
        asm volatile("bar.sync %0, %1;" :: "r"(1 + set), "r"(128) : "memory");

        for (int c = 0; c < 8; c++) {
            // prefetch chunk c+1
            if (c < 7) {
                #pragma unroll
                for (int m = 0; m < 4; m++) {
                    int kg = kb0 + 16 * (c + 1) + 4 * w4 + m;
                    v4[m] = __ldcg((const float4*)(hT + kg * 128 + 4 * lane));
                }
            }

            // compute chunk c (16 k)
            {
                const float* Ab = AsS + (c & 1) * (16 * 132) + 32 * w4 + 4 * bq;
                const float* Wk = Wd + (kb0 + 16 * c) * 32 + 8 * r4;
                #pragma unroll
                for (int k = 0; k < 16; k++) {
                    ulonglong2 a   = *(const ulonglong2*)(Ab + k * 132);
                    ulonglong2 w01 = *(const ulonglong2*)(Wk + k * 32);
                    ulonglong2 w23 = *(const ulonglong2*)(Wk + k * 32 + 4);
                    fma2(acc[0], a.x, w01.x);  fma2(acc[1], a.y, w01.x);
                    fma2(acc[2], a.x, w01.y);  fma2(acc[3], a.y, w01.y);
                    fma2(acc[4], a.x, w23.x);  fma2(acc[5], a.y, w23.x);
                    fma2(acc[6], a.x, w23.y);  fma2(acc[7], a.y, w23.y);
                }
            }

            // commit prefetched chunk
            if (c < 7) {
                float* dst = AsS + ((c + 1) & 1) * (16 * 132);
                #pragma unroll
                for (int m = 0; m < 4; m++)
                    *(float4*)(dst + (4 * w4 + m) * 132 + 4 * lane) = v4[m];
            }
            asm volatile("bar.sync %0, %1;" :: "r"(1 + set), "r"(128) : "memory");
        }

        // ---- park partial tiles ----
        #pragma unroll
        for (int r = 0; r < 4; r++) {
            ulonglong2 pr; pr.x = acc[2 * r]; pr.y = acc[2 * r + 1];
            *(ulonglong2*)(Gs + set * (16 * 132) + (4 * r4 + r) * 132
                           + 32 * w4 + 4 * bq) = pr;
        }
        __syncthreads();

        // ---- reduce 4 K-set partials + x_proj + gates ----
        {
            float xi = xq[0], xf = xq[1], xg = xq[2], xo = xq[3];
            #pragma unroll
            for (int s = 0; s < 4; s++) {
                const float* P = Gs + s * (16 * 132);
                xi += P[(0 + pc)  * 132 + pb];
                xf += P[(4 + pc)  * 132 + pb];
                xg += P[(8 + pc)  * 132 + pb];
                xo += P[(12 + pc) * 132 + pb];
            }
            if (t < len) {
                float ig = sigf(xi), fg = sigf(xf), og = sigf(xo);
                float gg = 2.f * sigf(2.f * xg) - 1.f;
                c_reg = fg * c_reg + ig * gg;
                h_reg = og * (2.f * sigf(2.f * c_reg) - 1.f);
            }
            g_hT[wb][hcol * 128 + pb] = h_reg;
        }

        // ---- grid barrier ----
        __threadfence();
        __syncthreads();
        if (tid == 0) {
            unsigned target = (unsigned)NBLK * (unsigned)(t + 1);
            atomicAdd(&g_arrive, 1u);
            while (*(volatile unsigned*)&g_arrive < target) { }
        }
        __syncthreads();
    }

    // ---- segment handoff ----
    g_c[pb * H + hcol] = c_reg;
}

// ---------------------------------------------------------------------------
// FC: out[b, v] = h_final[b, :] . W_fc[v, :] + b_fc[v]   (h read from g_hT[0])
// ---------------------------------------------------------------------------
__global__ void __launch_bounds__(256, 1)
k_fc(const float* __restrict__ Wfc, const float* __restrict__ bfc,
     float* __restrict__ out)
{
    __shared__ float As_[16][128];
    __shared__ float Bs_[16][128];

    const int vBase = blockIdx.x * 128;
    const int tid   = threadIdx.x;
    const int ty    = tid >> 4;
    const int tx    = tid & 15;

    const float* __restrict__ hT = g_hT[0];

    float acc[8][8];
    #pragma unroll
    for (int i = 0; i < 8; i++)
        #pragma unroll
        for (int j = 0; j < 8; j++) acc[i][j] = 0.f;

    for (int k0 = 0; k0 < H; k0 += 16) {
        #pragma unroll
        for (int r = 0; r < 8; r++) {
            int idx = tid + 256 * r;
            int k = idx >> 7, m = idx & 127;
            As_[k][m] = hT[(k0 + k) * 128 + m];       // coalesced
        }
        #pragma unroll
        for (int r = 0; r < 8; r++) {
            int idx = tid + 256 * r;
            int vv = idx >> 4, k = idx & 15;
            int gv = vBase + vv;
            Bs_[k][vv] = (gv < V) ? Wfc[gv * H + k0 + k] : 0.f;
        }
        __syncthreads();

        #pragma unroll
        for (int k = 0; k < 16; k++) {
            float a[8], b[8];
            *(float4*)&a[0] = *(const float4*)&As_[k][ty * 8];
            *(float4*)&a[4] = *(const float4*)&As_[k][ty * 8 + 4];
            *(float4*)&b[0] = *(const float4*)&Bs_[k][tx * 8];
            *(float4*)&b[4] = *(const float4*)&Bs_[k][tx * 8 + 4];
            #pragma unroll
            for (int i = 0; i < 8; i++)
                #pragma unroll
                for (int j = 0; j < 8; j++)
                    acc[i][j] = fmaf(a[i], b[j], acc[i][j]);
        }
        __syncthreads();
    }

    #pragma unroll
    for (int i = 0; i < 8; i++) {
        int m = ty * 8 + i;
        #pragma unroll
        for (int j = 0; j < 8; j++) {
            int gv = vBase + tx * 8 + j;
            if (gv < V) out[m * V + gv] = acc[i][j] + bfc[gv];
        }
    }
}

// ---------------------------------------------------------------------------
extern "C" void kernel_launch(void* const* d_in, const int* in_sizes, int n_in,
                              void* d_out, int out_size)
{
    const int*   tokens  = (const int*)  d_in[0];
    const int*   lengths = (const int*)  d_in[1];
    const float* emb     = (const float*)d_in[2];
    const float* Wih     = (const float*)d_in[3];
    const float* Whh     = (const float*)d_in[4];
    const float* bih     = (const float*)d_in[5];
    const float* bhh     = (const float*)d_in[6];
    const float* Wfc     = (const float*)d_in[7];
    const float* bfc     = (const float*)d_in[8];
    float* out = (float*)d_out;

    const int smemBytes = (16384 + 4 * 2 * 16 * 132 + 4 * 16 * 132) * 4;
    static bool attrSet = false;
    if (!attrSet) {
        cudaFuncSetAttribute(k_lstm, cudaFuncAttributeMaxDynamicSharedMemorySize,
                             smemBytes);
        attrSet = true;
    }

    k_init<<<(H * B + 255) / 256, 256>>>(tokens);
    dim3 xg(16, 512);
    k_xproj<<<xg, 256>>>(Wih, bih, bhh, emb);
    for (int seg = 0; seg < 4; seg++) {
        k_lstm<<<NBLK, NTHR, smemBytes>>>(lengths, Whh,
                                          seg * (L / 4), (seg + 1) * (L / 4));
    }
    k_fc<<<(V + 127) / 128, 256>>>(Wfc, bfc, out);
}